// round 8
// baseline (speedup 1.0000x reference)
#include <cuda_runtime.h>
#include <cuda_fp16.h>
#include <cuda_bf16.h>

// HashEncoder: 4-level dense-grid trilinear interpolation, F=4.
// R8: lane = u*8 + L*2 + fp  (u=point 0..3, L=level, fp=feature pair).
// Each warp-slot covers 4 points; warp loop is 4 slots (16 points/warp).
// Per slot each lane: 3 scalar pos LDGs, 2x LDG.128 (features 2fp,2fp+1 of
// its (point,level) cell: contiguous 32B of the 64B cell record), half2
// x/y lerps for both features, fp32 z lerp + rescale, one STG.64.
// fp16 cell records pre-scaled by 2^12; layout per (cell,feature):
// 4 half2 groups g(dy*2+dx) = {c(dx,dy,z0), c(dx,dy,z1)}.
//
// Level meta: res={32,43,56,74}, offsets={0,32768,112280,287896}, total=693120.

#define NPARAMS 693120
#define VAL_SCALE 4096.0f
#define INV_VAL_SCALE (1.0f / 4096.0f)

__device__ __half g_cells_h[NPARAMS * 32];   // 44.4 MB scratch (64B/cell)

__constant__ int c_res[4] = {32, 43, 56, 74};
__constant__ int c_off[4] = {0, 32768, 112280, 287896};

// ---------------------------------------------------------------- preprocess table
// thread t = gbase*2 + fp : builds records for features {2fp, 2fp+1}.
__global__ void __launch_bounds__(256)
build_cells(const float* __restrict__ tab)
{
    int t = blockIdx.x * blockDim.x + threadIdx.x;
    if (t >= NPARAMS * 2) return;

    int gbase = t >> 1;
    int fp = t & 1;

    int L = (gbase >= 32768) + (gbase >= 112280) + (gbase >= 287896);
    int res  = c_res[L];
    int off  = c_off[L];
    int res2 = res * res;
    int local = gbase - off;

    int z   = local / res2;          // padding cells may exceed grid; clamp below
    int rem = local - z * res2;
    int y   = rem / res;
    int x   = rem - y * res;

    float2 v[4][2];                  // [g=dy*2+dx][dz] = (feat 2fp, feat 2fp+1)
#pragma unroll
    for (int g = 0; g < 4; ++g) {
        int xi = min(x + (g & 1), res - 1);
        int yi = min(y + (g >> 1), res - 1);
#pragma unroll
        for (int dz = 0; dz < 2; ++dz) {
            int zi = min(z + dz, res - 1);
            int idx = off + xi + yi * res + zi * res2;
            float2 w = __ldg((const float2*)&tab[idx * 4 + 2 * fp]);
            v[g][dz] = make_float2(w.x * VAL_SCALE, w.y * VAL_SCALE);
        }
    }

    uint4 r0, r1;
    {
        half2 h0 = __floats2half2_rn(v[0][0].x, v[0][1].x);
        half2 h1 = __floats2half2_rn(v[1][0].x, v[1][1].x);
        half2 h2 = __floats2half2_rn(v[2][0].x, v[2][1].x);
        half2 h3 = __floats2half2_rn(v[3][0].x, v[3][1].x);
        r0.x = *(unsigned*)&h0; r0.y = *(unsigned*)&h1;
        r0.z = *(unsigned*)&h2; r0.w = *(unsigned*)&h3;
    }
    {
        half2 h0 = __floats2half2_rn(v[0][0].y, v[0][1].y);
        half2 h1 = __floats2half2_rn(v[1][0].y, v[1][1].y);
        half2 h2 = __floats2half2_rn(v[2][0].y, v[2][1].y);
        half2 h3 = __floats2half2_rn(v[3][0].y, v[3][1].y);
        r1.x = *(unsigned*)&h0; r1.y = *(unsigned*)&h1;
        r1.z = *(unsigned*)&h2; r1.w = *(unsigned*)&h3;
    }

    uint4* dst = (uint4*)g_cells_h;
    dst[gbase * 4 + 2 * fp]     = r0;
    dst[gbase * 4 + 2 * fp + 1] = r1;
}

// ---------------------------------------------------------------- main pass
template <bool GUARD>
__device__ __forceinline__ void
encode_body(const float* __restrict__ pos, float* __restrict__ out,
            const __half* __restrict__ cells_lf, float s,
            int res, int res2, int off,
            int p0, int u, int lane, int n)
{
#pragma unroll
    for (int k = 0; k < 4; ++k) {
        int p = p0 + 4 * k + u;
        bool valid = true;
        if (GUARD) { valid = (p < n); if (!valid) p = n - 1; }

        float x = __ldg(&pos[3 * p + 0]);
        float y = __ldg(&pos[3 * p + 1]);
        float z = __ldg(&pos[3 * p + 2]);

        float px = fmaf(x, s, 0.5f);
        float py = fmaf(y, s, 0.5f);
        float pz = fmaf(z, s, 0.5f);
        float gx = floorf(px), gy = floorf(py), gz = floorf(pz);
        float fx = px - gx, fy = py - gy, fz = pz - gz;
        int ix = (int)gx, iy = (int)gy, iz = (int)gz;

        int gbase = off + ix + iy * res + iz * res2;

        // 32B: records of features 2fp and 2fp+1 (contiguous in 64B cell rec).
        const __half* rp = cells_lf + (size_t)gbase * 32;
        uint4 A = __ldg((const uint4*)rp);        // feature 2fp
        uint4 B = __ldg((const uint4*)(rp + 8));  // feature 2fp+1

        half2 fx2 = __float2half2_rn(fx);
        half2 fy2 = __float2half2_rn(fy);

        // feature A
        half2 a0 = *(half2*)&A.x, a1 = *(half2*)&A.y;
        half2 a2 = *(half2*)&A.z, a3 = *(half2*)&A.w;
        half2 aa = __hfma2(fx2, __hsub2(a1, a0), a0);
        half2 ab = __hfma2(fx2, __hsub2(a3, a2), a2);
        half2 ac = __hfma2(fy2, __hsub2(ab, aa), aa);   // {z0,z1}

        // feature B
        half2 b0 = *(half2*)&B.x, b1 = *(half2*)&B.y;
        half2 b2 = *(half2*)&B.z, b3 = *(half2*)&B.w;
        half2 ba = __hfma2(fx2, __hsub2(b1, b0), b0);
        half2 bb = __hfma2(fx2, __hsub2(b3, b2), b2);
        half2 bc = __hfma2(fy2, __hsub2(bb, ba), ba);

        float alo = __low2float(ac), ahi = __high2float(ac);
        float blo = __low2float(bc), bhi = __high2float(bc);
        float ra = fmaf(fz, ahi - alo, alo) * INV_VAL_SCALE;
        float rb = fmaf(fz, bhi - blo, blo) * INV_VAL_SCALE;

        // out[(p0+4k+u)*16 + L*4 + 2fp + {0,1}] -> flat (p0+4k)*16 + lane*2
        if (!GUARD || valid)
            *(float2*)&out[(size_t)(p0 + 4 * k) * 16 + lane * 2] =
                make_float2(ra, rb);
    }
}

__global__ void __launch_bounds__(256, 5)
encode_kernel(const float* __restrict__ pos, float* __restrict__ out,
              float4 scales, int n)
{
    const int lane = threadIdx.x & 31;
    const int warp = (blockIdx.x * blockDim.x + threadIdx.x) >> 5;
    const int p0 = warp * 16;
    if (p0 >= n) return;

    const int u  = lane >> 3;           // point within slot (0..3)
    const int L  = (lane >> 1) & 3;     // level
    const int fp = lane & 1;            // feature pair

    const float s = (L < 2) ? (L == 0 ? scales.x : scales.y)
                            : (L == 2 ? scales.z : scales.w);
    const int res  = c_res[L];
    const int res2 = res * res;
    const int off  = c_off[L];
    const __half* cells_lf = g_cells_h + fp * 16;   // +0 or +32B

    if (p0 + 16 <= n)
        encode_body<false>(pos, out, cells_lf, s, res, res2, off, p0, u, lane, n);
    else
        encode_body<true>(pos, out, cells_lf, s, res, res2, off, p0, u, lane, n);
}

// ---------------------------------------------------------------- launcher
extern "C" void kernel_launch(void* const* d_in, const int* in_sizes, int n_in,
                              void* d_out, int out_size)
{
    const float* positions = (const float*)d_in[0];
    const float* table = (const float*)d_in[1];
    float* out = (float*)d_out;

    int n = in_sizes[0] / 3;

    // Level scales: double math, rounded to fp32 like JAX's weak promotion.
    double b = 1.3195079565048218;
    double p = 1.0;
    float s[4];
    for (int l = 0; l < 4; ++l) {
        s[l] = (float)(32.0 * p - 1.0);
        p *= b;
    }
    float4 scales = make_float4(s[0], s[1], s[2], s[3]);

    int bb = (NPARAMS * 2 + 255) / 256;
    build_cells<<<bb, 256>>>(table);

    int warps = (n + 15) / 16;
    int blocks = (warps * 32 + 255) / 256;
    encode_kernel<<<blocks, 256>>>(positions, out, scales, n);
}

// round 9
// speedup vs baseline: 1.0810x; 1.0810x over previous
#include <cuda_runtime.h>
#include <cuda_fp16.h>
#include <cuda_bf16.h>

// HashEncoder: 4-level dense-grid trilinear interpolation, F=4.
// R9 = R4 encode (lane = q*16 + L*4 + f, ONE 16B gather per lane per slot,
// 4 wf/point — the gather optimum) + warp-register position staging:
// 48 position floats loaded once per warp (2 coalesced LDGs), distributed
// per-slot with __shfl_sync. Inner loop has NO position loads, so gathers
// depend only on fixed-latency math. fp16 cell records (64B/cell, values
// pre-scaled by 2^12); per (cell,feature): 4 half2 groups g(dy*2+dx) =
// {c(dx,dy,z0), c(dx,dy,z1)}.
//
// Level meta: res={32,43,56,74}, offsets={0,32768,112280,287896}, total=693120.

#define NPARAMS 693120
#define VAL_SCALE 4096.0f
#define INV_VAL_SCALE (1.0f / 4096.0f)
#define FULLM 0xffffffffu

__device__ __half g_cells_h[NPARAMS * 32];   // 44.4 MB scratch (64B/cell)

__constant__ int c_res[4] = {32, 43, 56, 74};
__constant__ int c_off[4] = {0, 32768, 112280, 287896};

// ---------------------------------------------------------------- preprocess table
// thread t = gbase*2 + fp : builds records for features {2fp, 2fp+1}.
__global__ void __launch_bounds__(256)
build_cells(const float* __restrict__ tab)
{
    int t = blockIdx.x * blockDim.x + threadIdx.x;
    if (t >= NPARAMS * 2) return;

    int gbase = t >> 1;
    int fp = t & 1;

    int L = (gbase >= 32768) + (gbase >= 112280) + (gbase >= 287896);
    int res  = c_res[L];
    int off  = c_off[L];
    int res2 = res * res;
    int local = gbase - off;

    int z   = local / res2;          // padding cells may exceed grid; clamp below
    int rem = local - z * res2;
    int y   = rem / res;
    int x   = rem - y * res;

    float2 v[4][2];                  // [g=dy*2+dx][dz] = (feat 2fp, feat 2fp+1)
#pragma unroll
    for (int g = 0; g < 4; ++g) {
        int xi = min(x + (g & 1), res - 1);
        int yi = min(y + (g >> 1), res - 1);
#pragma unroll
        for (int dz = 0; dz < 2; ++dz) {
            int zi = min(z + dz, res - 1);
            int idx = off + xi + yi * res + zi * res2;
            float2 w = __ldg((const float2*)&tab[idx * 4 + 2 * fp]);
            v[g][dz] = make_float2(w.x * VAL_SCALE, w.y * VAL_SCALE);
        }
    }

    uint4 r0, r1;
    {
        half2 h0 = __floats2half2_rn(v[0][0].x, v[0][1].x);
        half2 h1 = __floats2half2_rn(v[1][0].x, v[1][1].x);
        half2 h2 = __floats2half2_rn(v[2][0].x, v[2][1].x);
        half2 h3 = __floats2half2_rn(v[3][0].x, v[3][1].x);
        r0.x = *(unsigned*)&h0; r0.y = *(unsigned*)&h1;
        r0.z = *(unsigned*)&h2; r0.w = *(unsigned*)&h3;
    }
    {
        half2 h0 = __floats2half2_rn(v[0][0].y, v[0][1].y);
        half2 h1 = __floats2half2_rn(v[1][0].y, v[1][1].y);
        half2 h2 = __floats2half2_rn(v[2][0].y, v[2][1].y);
        half2 h3 = __floats2half2_rn(v[3][0].y, v[3][1].y);
        r1.x = *(unsigned*)&h0; r1.y = *(unsigned*)&h1;
        r1.z = *(unsigned*)&h2; r1.w = *(unsigned*)&h3;
    }

    uint4* dst = (uint4*)g_cells_h;
    dst[gbase * 4 + 2 * fp]     = r0;
    dst[gbase * 4 + 2 * fp + 1] = r1;
}

// ---------------------------------------------------------------- main pass
template <bool GUARD>
__device__ __forceinline__ void
encode_body(const float* __restrict__ pos, float* __restrict__ out,
            const __half* __restrict__ cells_f, float s,
            int res, int res2, int off,
            int p0, int q, int lane, int n)
{
    // Stage the warp's 48 position floats in registers (2 coalesced LDGs).
    long fbase = (long)p0 * 3;
    long ftot  = (long)n * 3;
    long ia = fbase + lane;
    long ib = fbase + 32 + lane;
    if (GUARD) { if (ia >= ftot) ia = ftot - 1; if (ib >= ftot) ib = ftot - 1; }
    float pv_a = __ldg(&pos[ia]);
    float pv_b = (lane < 16) ? __ldg(&pos[ib]) : 0.0f;

#pragma unroll
    for (int k = 0; k < 8; ++k) {
        int p = p0 + 2 * k + q;
        int rb = 6 * k + 3 * q;      // raw float index of this lane's point.x

        float x, y, z;
        if (k <= 4) {                       // rb+2 <= 29 : all in pv_a
            x = __shfl_sync(FULLM, pv_a, rb);
            y = __shfl_sync(FULLM, pv_a, rb + 1);
            z = __shfl_sync(FULLM, pv_a, rb + 2);
        } else if (k == 5) {                // rb = 30(q0)/33(q1): straddles
            float xa = __shfl_sync(FULLM, pv_a, rb & 31);
            float xb = __shfl_sync(FULLM, pv_b, (rb - 32) & 31);
            x = (rb < 32) ? xa : xb;
            float ya = __shfl_sync(FULLM, pv_a, (rb + 1) & 31);
            float yb = __shfl_sync(FULLM, pv_b, (rb - 31) & 31);
            y = (rb + 1 < 32) ? ya : yb;
            z = __shfl_sync(FULLM, pv_b, rb - 30);   // 32/35 -> lanes 2/5... (rb+2-32)
        } else {                            // k >= 6 : all in pv_b
            x = __shfl_sync(FULLM, pv_b, rb - 32);
            y = __shfl_sync(FULLM, pv_b, rb - 31);
            z = __shfl_sync(FULLM, pv_b, rb - 30);
        }

        float px = fmaf(x, s, 0.5f);
        float py = fmaf(y, s, 0.5f);
        float pz = fmaf(z, s, 0.5f);
        float gx = floorf(px), gy = floorf(py), gz = floorf(pz);
        float fx = px - gx, fy = py - gy, fz = pz - gz;
        int ix = (int)gx, iy = (int)gy, iz = (int)gz;

        int gbase = off + ix + iy * res + iz * res2;

        // 16B: 4 half2 z-pair groups of this lane's feature.
        uint4 rec = __ldg((const uint4*)(cells_f + (size_t)gbase * 32));
        half2 g0 = *(half2*)&rec.x;   // (dx,dy)=(0,0), {z0,z1}
        half2 g1 = *(half2*)&rec.y;   // (1,0)
        half2 g2 = *(half2*)&rec.z;   // (0,1)
        half2 g3 = *(half2*)&rec.w;   // (1,1)

        half2 fx2 = __float2half2_rn(fx);
        half2 fy2 = __float2half2_rn(fy);

        half2 a = __hfma2(fx2, __hsub2(g1, g0), g0);   // y=0, both z
        half2 b = __hfma2(fx2, __hsub2(g3, g2), g2);   // y=1, both z
        half2 c = __hfma2(fy2, __hsub2(b, a), a);      // {z0, z1}

        float clo = __low2float(c);
        float chi = __high2float(c);
        float r = fmaf(fz, chi - clo, clo) * INV_VAL_SCALE;

        if (!GUARD || p < n)
            out[(size_t)p0 * 16 + 32 * k + lane] = r;
    }
}

__global__ void __launch_bounds__(256, 6)
encode_kernel(const float* __restrict__ pos, float* __restrict__ out,
              float4 scales, int n)
{
    const int lane = threadIdx.x & 31;
    const int warp = (blockIdx.x * blockDim.x + threadIdx.x) >> 5;
    const int p0 = warp * 16;
    if (p0 >= n) return;

    const int q = lane >> 4;            // point parity within slot
    const int L = (lane >> 2) & 3;      // level
    const int f = lane & 3;             // feature

    const float s = (L < 2) ? (L == 0 ? scales.x : scales.y)
                            : (L == 2 ? scales.z : scales.w);
    const int res  = c_res[L];
    const int res2 = res * res;
    const int off  = c_off[L];
    const __half* cells_f = g_cells_h + f * 8;

    if (p0 + 16 <= n)
        encode_body<false>(pos, out, cells_f, s, res, res2, off, p0, q, lane, n);
    else
        encode_body<true>(pos, out, cells_f, s, res, res2, off, p0, q, lane, n);
}

// ---------------------------------------------------------------- launcher
extern "C" void kernel_launch(void* const* d_in, const int* in_sizes, int n_in,
                              void* d_out, int out_size)
{
    const float* positions = (const float*)d_in[0];
    const float* table = (const float*)d_in[1];
    float* out = (float*)d_out;

    int n = in_sizes[0] / 3;

    // Level scales: double math, rounded to fp32 like JAX's weak promotion.
    double b = 1.3195079565048218;
    double p = 1.0;
    float s[4];
    for (int l = 0; l < 4; ++l) {
        s[l] = (float)(32.0 * p - 1.0);
        p *= b;
    }
    float4 scales = make_float4(s[0], s[1], s[2], s[3]);

    int bb = (NPARAMS * 2 + 255) / 256;
    build_cells<<<bb, 256>>>(table);

    int warps = (n + 15) / 16;
    int blocks = (warps * 32 + 255) / 256;
    encode_kernel<<<blocks, 256>>>(positions, out, scales, n);
}